// round 6
// baseline (speedup 1.0000x reference)
#include <cuda_runtime.h>
#include <cuda_bf16.h>
#include <math.h>
#include <stdint.h>

// ---------------- problem constants ----------------
#define T_STEPS 30
#define BATCH   32
#define HID     512
#define S_LEN   50
#define VOCAB   32000
#define GDIM    1536   // 3*H
#define XK      576    // 512 emb + 64 latent

// ---------------- fp32 scratch ----------------
__device__ float g_kc[S_LEN * BATCH * HID];
__device__ float g_kf[S_LEN * BATCH * HID];
__device__ float g_Pc[S_LEN * BATCH * GDIM];
__device__ float g_Pf[S_LEN * BATCH * GDIM];
__device__ float g_X[T_STEPS * BATCH * XK];
__device__ float g_Wg[GDIM * XK];
__device__ float g_gipre[T_STEPS * BATCH * GDIM];
__device__ float g_qT[1024 * 32];     // [row r = a*512+d][b]
__device__ float g_ghT[GDIM * 32];    // [row][b]
__device__ float g_attn[100 * 32];    // [(a*50+s)][b]
__device__ float g_h[BATCH * HID];
__device__ float g_reluh[T_STEPS * BATCH * HID];

// barrier state (self-resetting across graph replays)
__device__ unsigned g_bcount = 0;
__device__ unsigned g_bgen   = 0;

// ---------------- bf16 split (hi/lo) row-major operand buffers ----------------
__device__ __nv_bfloat16 g_cmh[1664 * 512],  g_cml[1664 * 512];
__device__ __nv_bfloat16 g_fmh[1664 * 512],  g_fml[1664 * 512];
__device__ __nv_bfloat16 g_cwmh[512 * 512],  g_cwml[512 * 512];
__device__ __nv_bfloat16 g_fwmh[512 * 512],  g_fwml[512 * 512];
__device__ __nv_bfloat16 g_wcch[1536 * 512], g_wccl[1536 * 512];
__device__ __nv_bfloat16 g_wcfh[1536 * 512], g_wcfl[1536 * 512];
__device__ __nv_bfloat16 g_wgh[1536 * 576],  g_wgl[1536 * 576];
__device__ __nv_bfloat16 g_xh[1024 * 576],   g_xl[1024 * 576];
__device__ __nv_bfloat16 g_rhh[1024 * 512],  g_rhl[1024 * 512];
__device__ __nv_bfloat16 g_wph[32000 * 512], g_wpl[32000 * 512];

// ---------------- math helpers ----------------
__device__ __forceinline__ float tanhx(float x) {
    float e = __expf(2.0f * x);
    return 1.0f - __fdividef(2.0f, e + 1.0f);
}
__device__ __forceinline__ float sigx(float x) {
    return __fdividef(1.0f, 1.0f + __expf(-x));
}

// ---------------- PTX helpers (sm_80-era, plain-sm_100-safe) ----------------
__device__ __forceinline__ uint32_t smem_u32(const void* p) {
    uint32_t a;
    asm("{ .reg .u64 t; cvta.to.shared.u64 t, %1; cvt.u32.u64 %0, t; }" : "=r"(a) : "l"(p));
    return a;
}
#define CP16(dst, src) asm volatile("cp.async.cg.shared.global [%0], [%1], 16;" :: "r"(dst), "l"(src))
#define CP_COMMIT()    asm volatile("cp.async.commit_group;")
#define CP_WAIT1()     asm volatile("cp.async.wait_group 1;")
#define CP_WAIT0()     asm volatile("cp.async.wait_group 0;")

__device__ __forceinline__ void ldsm4(uint32_t* r, uint32_t addr) {
    asm volatile("ldmatrix.sync.aligned.m8n8.x4.shared.b16 {%0,%1,%2,%3}, [%4];"
        : "=r"(r[0]), "=r"(r[1]), "=r"(r[2]), "=r"(r[3]) : "r"(addr));
}
__device__ __forceinline__ void mma_bf16(float* d, const uint32_t* a, const uint32_t* b) {
    asm volatile("mma.sync.aligned.m16n8k16.row.col.f32.bf16.bf16.f32 "
        "{%0,%1,%2,%3}, {%4,%5,%6,%7}, {%8,%9}, {%0,%1,%2,%3};"
        : "+f"(d[0]), "+f"(d[1]), "+f"(d[2]), "+f"(d[3])
        : "r"(a[0]), "r"(a[1]), "r"(a[2]), "r"(a[3]), "r"(b[0]), "r"(b[1]));
}

// ---------------- grid barrier (persistent kernel) ----------------
__device__ __forceinline__ void grid_barrier(int G) {
    __syncthreads();
    if (threadIdx.x == 0) {
        volatile unsigned* vgen = &g_bgen;
        unsigned gen = *vgen;
        __threadfence();
        unsigned c = atomicAdd(&g_bcount, 1u);
        if (c == (unsigned)G - 1u) {
            g_bcount = 0;
            __threadfence();
            *vgen = gen + 1u;
        } else {
            while (*vgen == gen) { }
        }
        __threadfence();
    }
    __syncthreads();
}

// ---------------- fp32 -> split bf16 conversion ----------------
__global__ void conv_split(const float* __restrict__ src, int ld, int colstart,
                           int R, int K, int Rpad,
                           __nv_bfloat16* __restrict__ hi, __nv_bfloat16* __restrict__ lo)
{
    const int gpr = K >> 3;
    const long total = (long)Rpad * gpr;
    for (long idx = (long)blockIdx.x * blockDim.x + threadIdx.x; idx < total;
         idx += (long)gridDim.x * blockDim.x) {
        int r = (int)(idx / gpr);
        int g = (int)(idx - (long)r * gpr);
        float v[8];
        if (r < R) {
            const float* p = src + (size_t)r * ld + colstart + g * 8;
            float4 u0 = *(const float4*)p;
            float4 u1 = *(const float4*)(p + 4);
            v[0] = u0.x; v[1] = u0.y; v[2] = u0.z; v[3] = u0.w;
            v[4] = u1.x; v[5] = u1.y; v[6] = u1.z; v[7] = u1.w;
        } else {
            #pragma unroll
            for (int j = 0; j < 8; j++) v[j] = 0.f;
        }
        __align__(16) unsigned short hb[8];
        __align__(16) unsigned short lb[8];
        #pragma unroll
        for (int j = 0; j < 8; j++) {
            __nv_bfloat16 h = __float2bfloat16(v[j]);
            float hf = __bfloat162float(h);
            __nv_bfloat16 l = __float2bfloat16(v[j] - hf);
            hb[j] = reinterpret_cast<unsigned short&>(h);
            lb[j] = reinterpret_cast<unsigned short&>(l);
        }
        size_t o = (size_t)r * K + (size_t)g * 8;
        *(uint4*)(hi + o) = *(const uint4*)hb;
        *(uint4*)(lo + o) = *(const uint4*)lb;
    }
}

// ---------------- HMMA split-bf16 NT GEMM (as R4, proven) ----------------
#define ROWB  144
#define TILEA (128 * ROWB)
#define STG   (2 * TILEA)
#define GSMEM (2 * STG)

__global__ void __launch_bounds__(256) mma_gemm(
    const __nv_bfloat16* __restrict__ Ah, const __nv_bfloat16* __restrict__ Al,
    const __nv_bfloat16* __restrict__ Bh, const __nv_bfloat16* __restrict__ Bl,
    int K, const float* __restrict__ bias, float* __restrict__ C,
    int Mreal, int Ncols, int outmode)
{
    extern __shared__ __align__(128) char sm[];
    const int tid = threadIdx.x;
    const int m0 = blockIdx.x * 128;
    const int n0 = blockIdx.y * 128;
    const int nch = K >> 6;
    const int niter = 3 * nch;
    const uint32_t base = smem_u32(sm);

    const int lane = tid & 31, w = tid >> 5;
    const int wm = w & 3, wn = w >> 2;

    float acc[2][8][4];
    #pragma unroll
    for (int a = 0; a < 2; a++)
        #pragma unroll
        for (int b = 0; b < 8; b++)
            #pragma unroll
            for (int c = 0; c < 4; c++) acc[a][b][c] = 0.f;

    const int lr[4] = { (tid + 0) >> 3, (tid + 256) >> 3, (tid + 512) >> 3, (tid + 768) >> 3 };
    const int lg = tid & 7;

    auto load_stage = [&](int i, int stage) {
        const int p  = i / nch;
        const int kc = i - p * nch;
        const __nv_bfloat16* Ag = ((p == 1) ? Al : Ah) + (size_t)m0 * K + kc * 64;
        const __nv_bfloat16* Bg = ((p == 2) ? Bl : Bh) + (size_t)n0 * K + kc * 64;
        const uint32_t dA = base + stage * STG;
        const uint32_t dB = dA + TILEA;
        #pragma unroll
        for (int j = 0; j < 4; j++) {
            const int r = lr[j];
            CP16(dA + r * ROWB + lg * 16, Ag + (size_t)r * K + lg * 8);
            CP16(dB + r * ROWB + lg * 16, Bg + (size_t)r * K + lg * 8);
        }
        CP_COMMIT();
    };

    load_stage(0, 0);

    for (int i = 0; i < niter; i++) {
        const int cur = i & 1;
        if (i + 1 < niter) { load_stage(i + 1, cur ^ 1); CP_WAIT1(); }
        else               { CP_WAIT0(); }
        __syncthreads();

        const uint32_t sA = base + cur * STG;
        const uint32_t sB = sA + TILEA;
        const uint32_t aBase = sA + (uint32_t)(wm * 32 + (lane & 15)) * ROWB + (uint32_t)(lane >> 4) * 16;
        const uint32_t bBase = sB + (uint32_t)(wn * 64 + (lane & 7) + ((lane >> 4) << 3)) * ROWB
                                  + (uint32_t)(((lane >> 3) & 1) << 4);

        #pragma unroll
        for (int ks = 0; ks < 4; ks++) {
            uint32_t af[2][4], bfr[4][4];
            ldsm4(af[0], aBase + ks * 32);
            ldsm4(af[1], aBase + 16 * ROWB + ks * 32);
            #pragma unroll
            for (int ni = 0; ni < 4; ni++)
                ldsm4(bfr[ni], bBase + ni * 16 * ROWB + ks * 32);
            #pragma unroll
            for (int mi = 0; mi < 2; mi++)
                #pragma unroll
                for (int ni = 0; ni < 4; ni++) {
                    mma_bf16(acc[mi][2 * ni],     af[mi], &bfr[ni][0]);
                    mma_bf16(acc[mi][2 * ni + 1], af[mi], &bfr[ni][2]);
                }
        }
        __syncthreads();
    }

    const int ncol0 = n0 + wn * 64 + (lane & 3) * 2;
    #pragma unroll
    for (int mi = 0; mi < 2; mi++) {
        const int ml = wm * 32 + mi * 16 + (lane >> 2);
        #pragma unroll
        for (int half = 0; half < 2; half++) {
            const int m = m0 + ml + half * 8;
            if (m >= Mreal) continue;
            size_t orow = outmode ? ((size_t)(m & 31) * T_STEPS + (m >> 5)) : (size_t)m;
            float* cr = C + orow * Ncols + ncol0;
            #pragma unroll
            for (int nj = 0; nj < 8; nj++) {
                const int c = ncol0 + nj * 8;
                float b0 = bias ? bias[c] : 0.f;
                float b1 = bias ? bias[c + 1] : 0.f;
                float2 v;
                v.x = acc[mi][nj][half * 2 + 0] + b0;
                v.y = acc[mi][nj][half * 2 + 1] + b1;
                *(float2*)(cr + nj * 8) = v;
            }
        }
    }
}

// ---------------- gather kernels ----------------
__global__ void gather_X(const int* __restrict__ target,
                         const float* __restrict__ emb,
                         const float* __restrict__ latent)
{
    const int m = blockIdx.x;
    const int t = m >> 5, b = m & 31;
    const int tok = (t == 0) ? 1 : target[(t - 1) * BATCH + b];
    float* xr = g_X + (size_t)m * XK;
    const float* er = emb + (size_t)tok * 512;
    for (int c = threadIdx.x; c < XK; c += blockDim.x)
        xr[c] = (c < 512) ? er[c] : latent[b * 64 + (c - 512)];
}

__global__ void gather_Wg(const float* __restrict__ Wih)
{
    const int n = blockIdx.x;
    float* wr = g_Wg + (size_t)n * XK;
    const float* src = Wih + (size_t)n * 1600;
    for (int c = threadIdx.x; c < XK; c += blockDim.x)
        wr[c] = (c < 512) ? src[c] : src[1536 + (c - 512)];
}

__global__ void copy_h(const float* __restrict__ src)
{
    const int i = blockIdx.x * blockDim.x + threadIdx.x;
    if (i < BATCH * HID) g_h[i] = src[i];
}

// ---------------- persistent decode loop ----------------
// grid = G (one block per SM), 256 threads, 3 phases per step + grid barriers.
__global__ void __launch_bounds__(256, 1) decode_persist(
    int G,
    const float* __restrict__ cWh, const float* __restrict__ cbh,
    const float* __restrict__ fWh, const float* __restrict__ fbh,
    const float* __restrict__ Whh, const float* __restrict__ bhh,
    const float* __restrict__ cWo, const float* __restrict__ cbo,
    const float* __restrict__ fWo, const float* __restrict__ fbo,
    const int* __restrict__ cmask, const int* __restrict__ fmask)
{
    extern __shared__ __align__(16) float4 sh4[];   // phase A: [32][129] float4
    float* sfl = (float*)sh4;

    const int tid  = threadIdx.x;
    const int lane = tid & 31;
    const int w    = tid >> 5;
    const int bx   = blockIdx.x;

    for (int t = 0; t < T_STEPS; t++) {
        // ======== Phase A: qgh — rows 0..2559 of stacked [cWh; fWh; Whh] @ h^T ========
        {
            // load h -> smem, layout sh4[b*129 + kk] (conflict-free float4)
            const float4* h4 = (const float4*)g_h;
            for (int i = tid; i < 32 * 128; i += 256) {
                int b = i >> 7, kk = i & 127;
                sh4[b * 129 + kk] = h4[i];
            }
            __syncthreads();

            // 2-row groups: 1280 groups over all warps, block-resident assignment
            for (int g = bx + G * w; g < 1280; g += 8 * G) {
                const int r0 = g * 2;
                const float* Wbase;
                const float* bp;
                if (r0 < 512)       { Wbase = cWh + (size_t)r0 * 512;          bp = cbh + r0; }
                else if (r0 < 1024) { Wbase = fWh + (size_t)(r0 - 512) * 512;  bp = fbh + (r0 - 512); }
                else                { Wbase = Whh + (size_t)(r0 - 1024) * 512; bp = bhh + (r0 - 1024); }
                const float4* W0 = (const float4*)Wbase;
                const float4* W1 = W0 + 128;
                const float4* hb = sh4 + lane * 129;

                float a0 = 0.f, a1 = 0.f;
                #pragma unroll 4
                for (int kk = 0; kk < 128; kk++) {
                    float4 hv = hb[kk];
                    float4 w0 = W0[kk];
                    float4 w1 = W1[kk];
                    a0 = fmaf(w0.x, hv.x, a0); a0 = fmaf(w0.y, hv.y, a0);
                    a0 = fmaf(w0.z, hv.z, a0); a0 = fmaf(w0.w, hv.w, a0);
                    a1 = fmaf(w1.x, hv.x, a1); a1 = fmaf(w1.y, hv.y, a1);
                    a1 = fmaf(w1.z, hv.z, a1); a1 = fmaf(w1.w, hv.w, a1);
                }
                float* d0 = (r0 < 1024) ? (g_qT + (size_t)r0 * 32) : (g_ghT + (size_t)(r0 - 1024) * 32);
                d0[lane]      = a0 + bp[0];
                d0[32 + lane] = a1 + bp[1];
            }
        }
        grid_barrier(G);

        // ======== Phase B: scores + softmax, block = (a, b), 64 blocks ========
        if (bx < 64) {
            const int a = bx >> 5;
            const int b = bx & 31;
            const float* kb = (a ? g_kf : g_kc) + (size_t)b * 512;
            const float4* Wo4 = (const float4*)(a ? fWo : cWo);
            const float bo = (a ? fbo : cbo)[0];
            const int* msk = a ? fmask : cmask;
            float* s_sc = sfl;   // [50]

            // per-lane q and Wo fragments: d = 4*lane + 128*j
            float4 wo[4];
            float qv[16];
            #pragma unroll
            for (int j = 0; j < 4; j++) {
                wo[j] = Wo4[lane + 32 * j];
                const int d = 4 * lane + 128 * j;
                qv[4 * j + 0] = g_qT[(size_t)(a * 512 + d + 0) * 32 + b];
                qv[4 * j + 1] = g_qT[(size_t)(a * 512 + d + 1) * 32 + b];
                qv[4 * j + 2] = g_qT[(size_t)(a * 512 + d + 2) * 32 + b];
                qv[4 * j + 3] = g_qT[(size_t)(a * 512 + d + 3) * 32 + b];
            }

            for (int s = w; s < S_LEN; s += 8) {
                const float4* kr = (const float4*)(kb + (size_t)s * 32 * 512);
                float acc = 0.f;
                #pragma unroll
                for (int j = 0; j < 4; j++) {
                    float4 kv = kr[lane + 32 * j];
                    acc = fmaf(wo[j].x, tanhx(qv[4 * j + 0] + kv.x), acc);
                    acc = fmaf(wo[j].y, tanhx(qv[4 * j + 1] + kv.y), acc);
                    acc = fmaf(wo[j].z, tanhx(qv[4 * j + 2] + kv.z), acc);
                    acc = fmaf(wo[j].w, tanhx(qv[4 * j + 3] + kv.w), acc);
                }
                #pragma unroll
                for (int o = 16; o; o >>= 1) acc += __shfl_xor_sync(0xffffffffu, acc, o);
                if (lane == 0) {
                    float v = acc + bo;
                    if (msk[s * 32 + b] == 0) v = -INFINITY;
                    s_sc[s] = v;
                }
            }
            __syncthreads();
            if (w == 0) {
                float v0 = s_sc[lane];
                float v1 = (lane < S_LEN - 32) ? s_sc[32 + lane] : -INFINITY;
                float mx = fmaxf(v0, v1);
                #pragma unroll
                for (int o = 16; o; o >>= 1) mx = fmaxf(mx, __shfl_xor_sync(0xffffffffu, mx, o));
                float e0 = __expf(v0 - mx);
                float e1 = (lane < S_LEN - 32) ? __expf(v1 - mx) : 0.f;
                float sm = e0 + e1;
                #pragma unroll
                for (int o = 16; o; o >>= 1) sm += __shfl_xor_sync(0xffffffffu, sm, o);
                float inv = __fdividef(1.f, sm);
                g_attn[(size_t)(a * 50 + lane) * 32 + b] = e0 * inv;
                if (lane < S_LEN - 32)
                    g_attn[(size_t)(a * 50 + 32 + lane) * 32 + b] = e1 * inv;
            }
        }
        grid_barrier(G);

        // ======== Phase C: gate — unit = (quarter, b), 128 blocks, s split over 2 halves ========
        if (bx < 128) {
            const int b = bx & 31;
            const int qd = bx >> 5;
            float* s_at = sfl;            // [100]
            float* s_ps = sfl + 128;      // [3][128] partials of upper half

            if (tid < 100) s_at[tid] = g_attn[(size_t)tid * 32 + b];
            __syncthreads();

            const int j = qd * 128 + (tid & 127);
            const int shalf = tid >> 7;
            float gr = 0.f, gz = 0.f, gn = 0.f;
            const int sbeg = shalf * 25;
            #pragma unroll 1
            for (int s = sbeg; s < sbeg + 25; s++) {
                const float ac = s_at[s];
                const float af = s_at[50 + s];
                const float* pc = g_Pc + (size_t)(s * 32 + b) * GDIM;
                const float* pf = g_Pf + (size_t)(s * 32 + b) * GDIM;
                gr = fmaf(ac, pc[j],        gr); gr = fmaf(af, pf[j],        gr);
                gz = fmaf(ac, pc[512 + j],  gz); gz = fmaf(af, pf[512 + j],  gz);
                gn = fmaf(ac, pc[1024 + j], gn); gn = fmaf(af, pf[1024 + j], gn);
            }
            if (shalf == 1) {
                s_ps[tid & 127]       = gr;
                s_ps[128 + (tid & 127)] = gz;
                s_ps[256 + (tid & 127)] = gn;
            }
            __syncthreads();
            if (shalf == 0) {
                gr += s_ps[tid];
                gz += s_ps[128 + tid];
                gn += s_ps[256 + tid];
                const float* gip = g_gipre + (size_t)(t * 32 + b) * GDIM;
                const float gir = gip[j]        + gr;
                const float giz = gip[512 + j]  + gz;
                const float gin = gip[1024 + j] + gn;
                const float ghr = g_ghT[(size_t)j * 32 + b];
                const float ghz = g_ghT[(size_t)(512 + j) * 32 + b];
                const float ghn = g_ghT[(size_t)(1024 + j) * 32 + b];
                const float r = sigx(gir + ghr);
                const float z = sigx(giz + ghz);
                const float n = tanhx(gin + r * ghn);
                const float hv = g_h[b * 512 + j];
                const float hn = (1.f - z) * n + z * hv;
                g_h[b * 512 + j] = hn;
                g_reluh[(size_t)(t * 32 + b) * 512 + j] = fmaxf(hn, 0.f);
            }
        }
        grid_barrier(G);
    }
}

// ---------------- launcher ----------------
static inline int conv_blocks(long Rpad, long K) {
    long total = Rpad * (K / 8);
    long blk = (total + 255) / 256;
    return (int)(blk > 8192 ? 8192 : blk);
}

extern "C" void kernel_launch(void* const* d_in, const int* in_sizes, int n_in,
                              void* d_out, int out_size)
{
    (void)in_sizes; (void)n_in; (void)out_size;

    const float* c_memory = (const float*)d_in[0];
    const int*   c_mask   = (const int*)  d_in[1];
    const float* f_memory = (const float*)d_in[2];
    const int*   f_mask   = (const int*)  d_in[3];
    const float* hidden   = (const float*)d_in[4];
    const float* latent   = (const float*)d_in[6];
    const int*   target   = (const int*)  d_in[7];
    const float* emb      = (const float*)d_in[8];
    const float* cW_h = (const float*)d_in[9];
    const float* cb_h = (const float*)d_in[10];
    const float* cW_m = (const float*)d_in[11];
    const float* cb_m = (const float*)d_in[12];
    const float* cW_o = (const float*)d_in[13];
    const float* cb_o = (const float*)d_in[14];
    const float* fW_h = (const float*)d_in[15];
    const float* fb_h = (const float*)d_in[16];
    const float* fW_m = (const float*)d_in[17];
    const float* fb_m = (const float*)d_in[18];
    const float* fW_o = (const float*)d_in[19];
    const float* fb_o = (const float*)d_in[20];
    const float* W_ih = (const float*)d_in[21];
    const float* b_ih = (const float*)d_in[22];
    const float* W_hh = (const float*)d_in[23];
    const float* b_hh = (const float*)d_in[24];
    const float* W_pr = (const float*)d_in[25];
    const float* b_pr = (const float*)d_in[26];
    float* out = (float*)d_out;

    float *kc, *kf, *Pc, *Pf, *X, *Wg, *gipre, *reluh;
    cudaGetSymbolAddress((void**)&kc,    g_kc);
    cudaGetSymbolAddress((void**)&kf,    g_kf);
    cudaGetSymbolAddress((void**)&Pc,    g_Pc);
    cudaGetSymbolAddress((void**)&Pf,    g_Pf);
    cudaGetSymbolAddress((void**)&X,     g_X);
    cudaGetSymbolAddress((void**)&Wg,    g_Wg);
    cudaGetSymbolAddress((void**)&gipre, g_gipre);
    cudaGetSymbolAddress((void**)&reluh, g_reluh);

    __nv_bfloat16 *cmh, *cml, *fmh, *fml, *cwmh, *cwml, *fwmh, *fwml;
    __nv_bfloat16 *wcch, *wccl, *wcfh, *wcfl, *wgh, *wgl, *xh, *xl, *rhh, *rhl, *wph, *wpl;
    cudaGetSymbolAddress((void**)&cmh,  g_cmh);  cudaGetSymbolAddress((void**)&cml,  g_cml);
    cudaGetSymbolAddress((void**)&fmh,  g_fmh);  cudaGetSymbolAddress((void**)&fml,  g_fml);
    cudaGetSymbolAddress((void**)&cwmh, g_cwmh); cudaGetSymbolAddress((void**)&cwml, g_cwml);
    cudaGetSymbolAddress((void**)&fwmh, g_fwmh); cudaGetSymbolAddress((void**)&fwml, g_fwml);
    cudaGetSymbolAddress((void**)&wcch, g_wcch); cudaGetSymbolAddress((void**)&wccl, g_wccl);
    cudaGetSymbolAddress((void**)&wcfh, g_wcfh); cudaGetSymbolAddress((void**)&wcfl, g_wcfl);
    cudaGetSymbolAddress((void**)&wgh,  g_wgh);  cudaGetSymbolAddress((void**)&wgl,  g_wgl);
    cudaGetSymbolAddress((void**)&xh,   g_xh);   cudaGetSymbolAddress((void**)&xl,   g_xl);
    cudaGetSymbolAddress((void**)&rhh,  g_rhh);  cudaGetSymbolAddress((void**)&rhl,  g_rhl);
    cudaGetSymbolAddress((void**)&wph,  g_wph);  cudaGetSymbolAddress((void**)&wpl,  g_wpl);

    int G = 0;
    cudaDeviceGetAttribute(&G, cudaDevAttrMultiProcessorCount, 0);
    if (G <= 0) G = 148;

    cudaFuncSetAttribute(mma_gemm, cudaFuncAttributeMaxDynamicSharedMemorySize, GSMEM);
    const int PERSIST_SMEM = 32 * 129 * 16;   // 66048 B
    cudaFuncSetAttribute(decode_persist, cudaFuncAttributeMaxDynamicSharedMemorySize, PERSIST_SMEM);

    // ---- gathers + conversions (step-invariant) ----
    gather_X<<<T_STEPS * BATCH, 256>>>(target, emb, latent);
    gather_Wg<<<GDIM, 256>>>(W_ih);
    copy_h<<<32, 512>>>(hidden);

    conv_split<<<conv_blocks(1664, 512), 256>>>(c_memory, 512, 0, 1600, 512, 1664, cmh, cml);
    conv_split<<<conv_blocks(1664, 512), 256>>>(f_memory, 512, 0, 1600, 512, 1664, fmh, fml);
    conv_split<<<conv_blocks(512, 512), 256>>>(cW_m, 512, 0, 512, 512, 512, cwmh, cwml);
    conv_split<<<conv_blocks(512, 512), 256>>>(fW_m, 512, 0, 512, 512, 512, fwmh, fwml);
    conv_split<<<conv_blocks(1536, 512), 256>>>(W_ih, 1600, 512,  1536, 512, 1536, wcch, wccl);
    conv_split<<<conv_blocks(1536, 512), 256>>>(W_ih, 1600, 1024, 1536, 512, 1536, wcfh, wcfl);
    conv_split<<<conv_blocks(1536, 576), 256>>>(Wg, 576, 0, 1536, 576, 1536, wgh, wgl);
    conv_split<<<conv_blocks(1024, 576), 256>>>(X, 576, 0, 960, 576, 1024, xh, xl);
    conv_split<<<conv_blocks(32000, 512), 256>>>(W_pr, 512, 0, 32000, 512, 32000, wph, wpl);

    // ---- precompute GEMMs (HMMA) ----
    mma_gemm<<<dim3(13, 4),  256, GSMEM>>>(cmh, cml, cwmh, cwml, 512, cb_m, kc, 1600, 512, 0);
    mma_gemm<<<dim3(13, 4),  256, GSMEM>>>(fmh, fml, fwmh, fwml, 512, fb_m, kf, 1600, 512, 0);
    mma_gemm<<<dim3(13, 12), 256, GSMEM>>>(cmh, cml, wcch, wccl, 512, nullptr, Pc, 1600, GDIM, 0);
    mma_gemm<<<dim3(13, 12), 256, GSMEM>>>(fmh, fml, wcfh, wcfl, 512, nullptr, Pf, 1600, GDIM, 0);
    mma_gemm<<<dim3(8, 12),  256, GSMEM>>>(xh, xl, wgh, wgl, 576, b_ih, gipre, 960, GDIM, 0);

    // ---- sequential decode: ONE persistent launch ----
    decode_persist<<<G, 256, PERSIST_SMEM>>>(G,
        cW_h, cb_h, fW_h, fb_h, W_hh, b_hh,
        cW_o, cb_o, fW_o, fb_o, c_mask, f_mask);

    // ---- deferred vocabulary projection (HMMA) ----
    conv_split<<<conv_blocks(1024, 512), 256>>>(reluh, 512, 0, 960, 512, 1024, rhh, rhl);
    mma_gemm<<<dim3(8, 250), 256, GSMEM>>>(rhh, rhl, wph, wpl, 512, b_pr, out, 960, VOCAB, 1);
}

// round 7
// speedup vs baseline: 1.0868x; 1.0868x over previous
#include <cuda_runtime.h>
#include <cuda_bf16.h>
#include <math.h>
#include <stdint.h>

// ---------------- problem constants ----------------
#define T_STEPS 30
#define BATCH   32
#define HID     512
#define S_LEN   50
#define VOCAB   32000
#define GDIM    1536   // 3*H
#define XK      576    // 512 emb + 64 latent

// ---------------- fp32 scratch ----------------
__device__ float g_kc[S_LEN * BATCH * HID];
__device__ float g_kf[S_LEN * BATCH * HID];
__device__ float g_Pc[S_LEN * BATCH * GDIM];
__device__ float g_Pf[S_LEN * BATCH * GDIM];
__device__ float g_X[T_STEPS * BATCH * XK];
__device__ float g_Wg[GDIM * XK];
__device__ float g_gipre[T_STEPS * BATCH * GDIM];
__device__ float g_qT[1024 * 32];     // [row r = a*512+d][b]
__device__ float g_ghT[GDIM * 32];    // [row][b]
__device__ float g_attn[100 * 32];    // [(a*50+s)][b]
__device__ float g_h[BATCH * HID];
__device__ float g_reluh[T_STEPS * BATCH * HID];

// ---------------- bf16 split (hi/lo) row-major operand buffers ----------------
__device__ __nv_bfloat16 g_cmh[1664 * 512],  g_cml[1664 * 512];
__device__ __nv_bfloat16 g_fmh[1664 * 512],  g_fml[1664 * 512];
__device__ __nv_bfloat16 g_cwmh[512 * 512],  g_cwml[512 * 512];
__device__ __nv_bfloat16 g_fwmh[512 * 512],  g_fwml[512 * 512];
__device__ __nv_bfloat16 g_wcch[1536 * 512], g_wccl[1536 * 512];
__device__ __nv_bfloat16 g_wcfh[1536 * 512], g_wcfl[1536 * 512];
__device__ __nv_bfloat16 g_wgh[1536 * 576],  g_wgl[1536 * 576];
__device__ __nv_bfloat16 g_xh[1024 * 576],   g_xl[1024 * 576];
__device__ __nv_bfloat16 g_rhh[1024 * 512],  g_rhl[1024 * 512];
__device__ __nv_bfloat16 g_wph[32000 * 512], g_wpl[32000 * 512];

// ---------------- math helpers ----------------
__device__ __forceinline__ float tanhx(float x) {
    float e = __expf(2.0f * x);
    return 1.0f - __fdividef(2.0f, e + 1.0f);
}
__device__ __forceinline__ float sigx(float x) {
    return __fdividef(1.0f, 1.0f + __expf(-x));
}

// ---------------- PTX helpers (sm_80-era, plain-sm_100-safe) ----------------
__device__ __forceinline__ uint32_t smem_u32(const void* p) {
    uint32_t a;
    asm("{ .reg .u64 t; cvta.to.shared.u64 t, %1; cvt.u32.u64 %0, t; }" : "=r"(a) : "l"(p));
    return a;
}
#define CP16(dst, src) asm volatile("cp.async.cg.shared.global [%0], [%1], 16;" :: "r"(dst), "l"(src))
#define CP_COMMIT()    asm volatile("cp.async.commit_group;")
#define CP_WAIT1()     asm volatile("cp.async.wait_group 1;")
#define CP_WAIT0()     asm volatile("cp.async.wait_group 0;")

__device__ __forceinline__ void ldsm4(uint32_t* r, uint32_t addr) {
    asm volatile("ldmatrix.sync.aligned.m8n8.x4.shared.b16 {%0,%1,%2,%3}, [%4];"
        : "=r"(r[0]), "=r"(r[1]), "=r"(r[2]), "=r"(r[3]) : "r"(addr));
}
__device__ __forceinline__ void mma_bf16(float* d, const uint32_t* a, const uint32_t* b) {
    asm volatile("mma.sync.aligned.m16n8k16.row.col.f32.bf16.bf16.f32 "
        "{%0,%1,%2,%3}, {%4,%5,%6,%7}, {%8,%9}, {%0,%1,%2,%3};"
        : "+f"(d[0]), "+f"(d[1]), "+f"(d[2]), "+f"(d[3])
        : "r"(a[0]), "r"(a[1]), "r"(a[2]), "r"(a[3]), "r"(b[0]), "r"(b[1]));
}

// ---------------- fp32 -> split bf16 conversion ----------------
__global__ void conv_split(const float* __restrict__ src, int ld, int colstart,
                           int R, int K, int Rpad,
                           __nv_bfloat16* __restrict__ hi, __nv_bfloat16* __restrict__ lo)
{
    const int gpr = K >> 3;
    const long total = (long)Rpad * gpr;
    for (long idx = (long)blockIdx.x * blockDim.x + threadIdx.x; idx < total;
         idx += (long)gridDim.x * blockDim.x) {
        int r = (int)(idx / gpr);
        int g = (int)(idx - (long)r * gpr);
        float v[8];
        if (r < R) {
            const float* p = src + (size_t)r * ld + colstart + g * 8;
            float4 u0 = *(const float4*)p;
            float4 u1 = *(const float4*)(p + 4);
            v[0] = u0.x; v[1] = u0.y; v[2] = u0.z; v[3] = u0.w;
            v[4] = u1.x; v[5] = u1.y; v[6] = u1.z; v[7] = u1.w;
        } else {
            #pragma unroll
            for (int j = 0; j < 8; j++) v[j] = 0.f;
        }
        __align__(16) unsigned short hb[8];
        __align__(16) unsigned short lb[8];
        #pragma unroll
        for (int j = 0; j < 8; j++) {
            __nv_bfloat16 h = __float2bfloat16(v[j]);
            float hf = __bfloat162float(h);
            __nv_bfloat16 l = __float2bfloat16(v[j] - hf);
            hb[j] = reinterpret_cast<unsigned short&>(h);
            lb[j] = reinterpret_cast<unsigned short&>(l);
        }
        size_t o = (size_t)r * K + (size_t)g * 8;
        *(uint4*)(hi + o) = *(const uint4*)hb;
        *(uint4*)(lo + o) = *(const uint4*)lb;
    }
}

// ---------------- HMMA split-bf16 NT GEMM (proven R4) ----------------
#define ROWB  144
#define TILEA (128 * ROWB)
#define STG   (2 * TILEA)
#define GSMEM (2 * STG)

__global__ void __launch_bounds__(256) mma_gemm(
    const __nv_bfloat16* __restrict__ Ah, const __nv_bfloat16* __restrict__ Al,
    const __nv_bfloat16* __restrict__ Bh, const __nv_bfloat16* __restrict__ Bl,
    int K, const float* __restrict__ bias, float* __restrict__ C,
    int Mreal, int Ncols, int outmode)
{
    extern __shared__ __align__(128) char sm[];
    const int tid = threadIdx.x;
    const int m0 = blockIdx.x * 128;
    const int n0 = blockIdx.y * 128;
    const int nch = K >> 6;
    const int niter = 3 * nch;
    const uint32_t base = smem_u32(sm);

    const int lane = tid & 31, w = tid >> 5;
    const int wm = w & 3, wn = w >> 2;

    float acc[2][8][4];
    #pragma unroll
    for (int a = 0; a < 2; a++)
        #pragma unroll
        for (int b = 0; b < 8; b++)
            #pragma unroll
            for (int c = 0; c < 4; c++) acc[a][b][c] = 0.f;

    const int lr[4] = { (tid + 0) >> 3, (tid + 256) >> 3, (tid + 512) >> 3, (tid + 768) >> 3 };
    const int lg = tid & 7;

    auto load_stage = [&](int i, int stage) {
        const int p  = i / nch;
        const int kc = i - p * nch;
        const __nv_bfloat16* Ag = ((p == 1) ? Al : Ah) + (size_t)m0 * K + kc * 64;
        const __nv_bfloat16* Bg = ((p == 2) ? Bl : Bh) + (size_t)n0 * K + kc * 64;
        const uint32_t dA = base + stage * STG;
        const uint32_t dB = dA + TILEA;
        #pragma unroll
        for (int j = 0; j < 4; j++) {
            const int r = lr[j];
            CP16(dA + r * ROWB + lg * 16, Ag + (size_t)r * K + lg * 8);
            CP16(dB + r * ROWB + lg * 16, Bg + (size_t)r * K + lg * 8);
        }
        CP_COMMIT();
    };

    load_stage(0, 0);

    for (int i = 0; i < niter; i++) {
        const int cur = i & 1;
        if (i + 1 < niter) { load_stage(i + 1, cur ^ 1); CP_WAIT1(); }
        else               { CP_WAIT0(); }
        __syncthreads();

        const uint32_t sA = base + cur * STG;
        const uint32_t sB = sA + TILEA;
        const uint32_t aBase = sA + (uint32_t)(wm * 32 + (lane & 15)) * ROWB + (uint32_t)(lane >> 4) * 16;
        const uint32_t bBase = sB + (uint32_t)(wn * 64 + (lane & 7) + ((lane >> 4) << 3)) * ROWB
                                  + (uint32_t)(((lane >> 3) & 1) << 4);

        #pragma unroll
        for (int ks = 0; ks < 4; ks++) {
            uint32_t af[2][4], bfr[4][4];
            ldsm4(af[0], aBase + ks * 32);
            ldsm4(af[1], aBase + 16 * ROWB + ks * 32);
            #pragma unroll
            for (int ni = 0; ni < 4; ni++)
                ldsm4(bfr[ni], bBase + ni * 16 * ROWB + ks * 32);
            #pragma unroll
            for (int mi = 0; mi < 2; mi++)
                #pragma unroll
                for (int ni = 0; ni < 4; ni++) {
                    mma_bf16(acc[mi][2 * ni],     af[mi], &bfr[ni][0]);
                    mma_bf16(acc[mi][2 * ni + 1], af[mi], &bfr[ni][2]);
                }
        }
        __syncthreads();
    }

    const int ncol0 = n0 + wn * 64 + (lane & 3) * 2;
    #pragma unroll
    for (int mi = 0; mi < 2; mi++) {
        const int ml = wm * 32 + mi * 16 + (lane >> 2);
        #pragma unroll
        for (int half = 0; half < 2; half++) {
            const int m = m0 + ml + half * 8;
            if (m >= Mreal) continue;
            size_t orow = outmode ? ((size_t)(m & 31) * T_STEPS + (m >> 5)) : (size_t)m;
            float* cr = C + orow * Ncols + ncol0;
            #pragma unroll
            for (int nj = 0; nj < 8; nj++) {
                const int c = ncol0 + nj * 8;
                float b0 = bias ? bias[c] : 0.f;
                float b1 = bias ? bias[c + 1] : 0.f;
                float2 v;
                v.x = acc[mi][nj][half * 2 + 0] + b0;
                v.y = acc[mi][nj][half * 2 + 1] + b1;
                *(float2*)(cr + nj * 8) = v;
            }
        }
    }
}

// ---------------- gather kernels ----------------
__global__ void gather_X(const int* __restrict__ target,
                         const float* __restrict__ emb,
                         const float* __restrict__ latent)
{
    const int m = blockIdx.x;
    const int t = m >> 5, b = m & 31;
    const int tok = (t == 0) ? 1 : target[(t - 1) * BATCH + b];
    float* xr = g_X + (size_t)m * XK;
    const float* er = emb + (size_t)tok * 512;
    for (int c = threadIdx.x; c < XK; c += blockDim.x)
        xr[c] = (c < 512) ? er[c] : latent[b * 64 + (c - 512)];
}

__global__ void gather_Wg(const float* __restrict__ Wih)
{
    const int n = blockIdx.x;
    float* wr = g_Wg + (size_t)n * XK;
    const float* src = Wih + (size_t)n * 1600;
    for (int c = threadIdx.x; c < XK; c += blockDim.x)
        wr[c] = (c < 512) ? src[c] : src[1536 + (c - 512)];
}

__global__ void copy_h(const float* __restrict__ src)
{
    const int i = blockIdx.x * blockDim.x + threadIdx.x;
    if (i < BATCH * HID) g_h[i] = src[i];
}

// ---------------- decode step A v2: weights read ONCE, all batches per block ----------------
// grid (160) x 256: block = 16 consecutive rows of the stacked [cWh; fWh; Whh],
// warp = 2 rows x all 32 batches (lane = batch). h transposed in smem [32][133] float4.
__global__ void __launch_bounds__(256) step_qgh2(
    const float* __restrict__ cWh, const float* __restrict__ cbh,
    const float* __restrict__ fWh, const float* __restrict__ fbh,
    const float* __restrict__ Whh, const float* __restrict__ bhh)
{
    extern __shared__ __align__(16) float4 sh4[];   // [32][133]
    const int tid = threadIdx.x;
    const int lane = tid & 31;
    const int w = tid >> 5;

    const float4* h4 = (const float4*)g_h;
    #pragma unroll
    for (int i = tid; i < 32 * 128; i += 256) {
        const int b = i >> 7, kk = i & 127;
        sh4[b * 133 + kk] = h4[i];
    }
    __syncthreads();

    const int r0 = blockIdx.x * 16 + w * 2;
    const float* Wb;
    const float* bp;
    float* dst;
    if (r0 < 512)       { Wb = cWh + (size_t)r0 * 512;          bp = cbh + r0;          dst = g_qT  + (size_t)r0 * 32; }
    else if (r0 < 1024) { Wb = fWh + (size_t)(r0 - 512) * 512;  bp = fbh + (r0 - 512);  dst = g_qT  + (size_t)r0 * 32; }
    else                { Wb = Whh + (size_t)(r0 - 1024) * 512; bp = bhh + (r0 - 1024); dst = g_ghT + (size_t)(r0 - 1024) * 32; }

    const float4* W0 = (const float4*)Wb;
    const float4* W1 = W0 + 128;
    const float4* hb = sh4 + lane * 133;

    float a0 = 0.f, a1 = 0.f;
    #pragma unroll 8
    for (int kk = 0; kk < 128; kk++) {
        const float4 hv = hb[kk];
        const float4 w0 = W0[kk];
        const float4 w1 = W1[kk];
        a0 = fmaf(w0.x, hv.x, a0); a0 = fmaf(w0.y, hv.y, a0);
        a0 = fmaf(w0.z, hv.z, a0); a0 = fmaf(w0.w, hv.w, a0);
        a1 = fmaf(w1.x, hv.x, a1); a1 = fmaf(w1.y, hv.y, a1);
        a1 = fmaf(w1.z, hv.z, a1); a1 = fmaf(w1.w, hv.w, a1);
    }
    dst[lane]      = a0 + bp[0];
    dst[32 + lane] = a1 + bp[1];
}

// ---------------- decode step B v2: fused scores + softmax, block = (a, b) ----------------
__global__ void __launch_bounds__(256) step_score2(
    const float* __restrict__ cWo, const float* __restrict__ cbo,
    const float* __restrict__ fWo, const float* __restrict__ fbo,
    const int* __restrict__ cmask, const int* __restrict__ fmask)
{
    __shared__ float s_sc[S_LEN];
    const int a = blockIdx.x >> 5;
    const int b = blockIdx.x & 31;
    const int tid = threadIdx.x;
    const int lane = tid & 31;
    const int w = tid >> 5;

    const float* kb = (a ? g_kf : g_kc) + (size_t)b * 512;
    const float4* Wo4 = (const float4*)(a ? fWo : cWo);
    const float bo = (a ? fbo : cbo)[0];
    const int* msk = a ? fmask : cmask;

    float4 wo[4];
    float qv[16];
    #pragma unroll
    for (int j = 0; j < 4; j++) {
        wo[j] = Wo4[lane + 32 * j];
        const int d = 4 * lane + 128 * j;
        qv[4 * j + 0] = g_qT[(size_t)(a * 512 + d + 0) * 32 + b];
        qv[4 * j + 1] = g_qT[(size_t)(a * 512 + d + 1) * 32 + b];
        qv[4 * j + 2] = g_qT[(size_t)(a * 512 + d + 2) * 32 + b];
        qv[4 * j + 3] = g_qT[(size_t)(a * 512 + d + 3) * 32 + b];
    }

    for (int s = w; s < S_LEN; s += 8) {
        const float4* kr = (const float4*)(kb + (size_t)s * 32 * 512);
        float acc = 0.f;
        #pragma unroll
        for (int j = 0; j < 4; j++) {
            float4 kv = kr[lane + 32 * j];
            acc = fmaf(wo[j].x, tanhx(qv[4 * j + 0] + kv.x), acc);
            acc = fmaf(wo[j].y, tanhx(qv[4 * j + 1] + kv.y), acc);
            acc = fmaf(wo[j].z, tanhx(qv[4 * j + 2] + kv.z), acc);
            acc = fmaf(wo[j].w, tanhx(qv[4 * j + 3] + kv.w), acc);
        }
        #pragma unroll
        for (int o = 16; o; o >>= 1) acc += __shfl_xor_sync(0xffffffffu, acc, o);
        if (lane == 0) {
            float v = acc + bo;
            if (msk[s * 32 + b] == 0) v = -INFINITY;
            s_sc[s] = v;
        }
    }
    __syncthreads();
    if (w == 0) {
        float v0 = s_sc[lane];
        float v1 = (lane < S_LEN - 32) ? s_sc[32 + lane] : -INFINITY;
        float mx = fmaxf(v0, v1);
        #pragma unroll
        for (int o = 16; o; o >>= 1) mx = fmaxf(mx, __shfl_xor_sync(0xffffffffu, mx, o));
        float e0 = __expf(v0 - mx);
        float e1 = (lane < S_LEN - 32) ? __expf(v1 - mx) : 0.f;
        float sm = e0 + e1;
        #pragma unroll
        for (int o = 16; o; o >>= 1) sm += __shfl_xor_sync(0xffffffffu, sm, o);
        float inv = __fdividef(1.f, sm);
        g_attn[(size_t)(a * 50 + lane) * 32 + b] = e0 * inv;
        if (lane < S_LEN - 32)
            g_attn[(size_t)(a * 50 + 32 + lane) * 32 + b] = e1 * inv;
    }
}

// ---------------- decode step C v2: softmax-weighted P + GRU gates ----------------
// grid (4, 32) x 256: block = (quarter, b), s split into 2 halves across threads.
__global__ void __launch_bounds__(256) step_gate2(int tstep)
{
    __shared__ float s_at[100];
    __shared__ float s_ps[384];
    const int qd = blockIdx.x;
    const int b  = blockIdx.y;
    const int tid = threadIdx.x;

    if (tid < 100) s_at[tid] = g_attn[(size_t)tid * 32 + b];
    __syncthreads();

    const int j = qd * 128 + (tid & 127);
    const int shalf = tid >> 7;
    float gr = 0.f, gz = 0.f, gn = 0.f;
    const int sbeg = shalf * 25;
    #pragma unroll 1
    for (int s = sbeg; s < sbeg + 25; s++) {
        const float ac = s_at[s];
        const float af = s_at[50 + s];
        const float* pc = g_Pc + (size_t)(s * 32 + b) * GDIM;
        const float* pf = g_Pf + (size_t)(s * 32 + b) * GDIM;
        gr = fmaf(ac, pc[j],        gr); gr = fmaf(af, pf[j],        gr);
        gz = fmaf(ac, pc[512 + j],  gz); gz = fmaf(af, pf[512 + j],  gz);
        gn = fmaf(ac, pc[1024 + j], gn); gn = fmaf(af, pf[1024 + j], gn);
    }
    if (shalf == 1) {
        s_ps[tid & 127]         = gr;
        s_ps[128 + (tid & 127)] = gz;
        s_ps[256 + (tid & 127)] = gn;
    }
    __syncthreads();
    if (shalf == 0) {
        gr += s_ps[tid];
        gz += s_ps[128 + tid];
        gn += s_ps[256 + tid];
        const float* gip = g_gipre + (size_t)(tstep * 32 + b) * GDIM;
        const float gir = gip[j]        + gr;
        const float giz = gip[512 + j]  + gz;
        const float gin = gip[1024 + j] + gn;
        const float ghr = g_ghT[(size_t)j * 32 + b];
        const float ghz = g_ghT[(size_t)(512 + j) * 32 + b];
        const float ghn = g_ghT[(size_t)(1024 + j) * 32 + b];
        const float r = sigx(gir + ghr);
        const float z = sigx(giz + ghz);
        const float n = tanhx(gin + r * ghn);
        const float hv = g_h[b * 512 + j];
        const float hn = (1.f - z) * n + z * hv;
        g_h[b * 512 + j] = hn;
        g_reluh[(size_t)(tstep * 32 + b) * 512 + j] = fmaxf(hn, 0.f);
    }
}

// ---------------- launcher ----------------
static inline int conv_blocks(long Rpad, long K) {
    long total = Rpad * (K / 8);
    long blk = (total + 255) / 256;
    return (int)(blk > 8192 ? 8192 : blk);
}

extern "C" void kernel_launch(void* const* d_in, const int* in_sizes, int n_in,
                              void* d_out, int out_size)
{
    (void)in_sizes; (void)n_in; (void)out_size;

    const float* c_memory = (const float*)d_in[0];
    const int*   c_mask   = (const int*)  d_in[1];
    const float* f_memory = (const float*)d_in[2];
    const int*   f_mask   = (const int*)  d_in[3];
    const float* hidden   = (const float*)d_in[4];
    const float* latent   = (const float*)d_in[6];
    const int*   target   = (const int*)  d_in[7];
    const float* emb      = (const float*)d_in[8];
    const float* cW_h = (const float*)d_in[9];
    const float* cb_h = (const float*)d_in[10];
    const float* cW_m = (const float*)d_in[11];
    const float* cb_m = (const float*)d_in[12];
    const float* cW_o = (const float*)d_in[13];
    const float* cb_o = (const float*)d_in[14];
    const float* fW_h = (const float*)d_in[15];
    const float* fb_h = (const float*)d_in[16];
    const float* fW_m = (const float*)d_in[17];
    const float* fb_m = (const float*)d_in[18];
    const float* fW_o = (const float*)d_in[19];
    const float* fb_o = (const float*)d_in[20];
    const float* W_ih = (const float*)d_in[21];
    const float* b_ih = (const float*)d_in[22];
    const float* W_hh = (const float*)d_in[23];
    const float* b_hh = (const float*)d_in[24];
    const float* W_pr = (const float*)d_in[25];
    const float* b_pr = (const float*)d_in[26];
    float* out = (float*)d_out;

    float *kc, *kf, *Pc, *Pf, *X, *Wg, *gipre, *reluh;
    cudaGetSymbolAddress((void**)&kc,    g_kc);
    cudaGetSymbolAddress((void**)&kf,    g_kf);
    cudaGetSymbolAddress((void**)&Pc,    g_Pc);
    cudaGetSymbolAddress((void**)&Pf,    g_Pf);
    cudaGetSymbolAddress((void**)&X,     g_X);
    cudaGetSymbolAddress((void**)&Wg,    g_Wg);
    cudaGetSymbolAddress((void**)&gipre, g_gipre);
    cudaGetSymbolAddress((void**)&reluh, g_reluh);

    __nv_bfloat16 *cmh, *cml, *fmh, *fml, *cwmh, *cwml, *fwmh, *fwml;
    __nv_bfloat16 *wcch, *wccl, *wcfh, *wcfl, *wgh, *wgl, *xh, *xl, *rhh, *rhl, *wph, *wpl;
    cudaGetSymbolAddress((void**)&cmh,  g_cmh);  cudaGetSymbolAddress((void**)&cml,  g_cml);
    cudaGetSymbolAddress((void**)&fmh,  g_fmh);  cudaGetSymbolAddress((void**)&fml,  g_fml);
    cudaGetSymbolAddress((void**)&cwmh, g_cwmh); cudaGetSymbolAddress((void**)&cwml, g_cwml);
    cudaGetSymbolAddress((void**)&fwmh, g_fwmh); cudaGetSymbolAddress((void**)&fwml, g_fwml);
    cudaGetSymbolAddress((void**)&wcch, g_wcch); cudaGetSymbolAddress((void**)&wccl, g_wccl);
    cudaGetSymbolAddress((void**)&wcfh, g_wcfh); cudaGetSymbolAddress((void**)&wcfl, g_wcfl);
    cudaGetSymbolAddress((void**)&wgh,  g_wgh);  cudaGetSymbolAddress((void**)&wgl,  g_wgl);
    cudaGetSymbolAddress((void**)&xh,   g_xh);   cudaGetSymbolAddress((void**)&xl,   g_xl);
    cudaGetSymbolAddress((void**)&rhh,  g_rhh);  cudaGetSymbolAddress((void**)&rhl,  g_rhl);
    cudaGetSymbolAddress((void**)&wph,  g_wph);  cudaGetSymbolAddress((void**)&wpl,  g_wpl);

    cudaFuncSetAttribute(mma_gemm, cudaFuncAttributeMaxDynamicSharedMemorySize, GSMEM);
    const int QGH_SMEM = 32 * 133 * 16;   // 68096 B
    cudaFuncSetAttribute(step_qgh2, cudaFuncAttributeMaxDynamicSharedMemorySize, QGH_SMEM);

    // ---- gathers + conversions (step-invariant) ----
    gather_X<<<T_STEPS * BATCH, 256>>>(target, emb, latent);
    gather_Wg<<<GDIM, 256>>>(W_ih);
    copy_h<<<32, 512>>>(hidden);

    conv_split<<<conv_blocks(1664, 512), 256>>>(c_memory, 512, 0, 1600, 512, 1664, cmh, cml);
    conv_split<<<conv_blocks(1664, 512), 256>>>(f_memory, 512, 0, 1600, 512, 1664, fmh, fml);
    conv_split<<<conv_blocks(512, 512), 256>>>(cW_m, 512, 0, 512, 512, 512, cwmh, cwml);
    conv_split<<<conv_blocks(512, 512), 256>>>(fW_m, 512, 0, 512, 512, 512, fwmh, fwml);
    conv_split<<<conv_blocks(1536, 512), 256>>>(W_ih, 1600, 512,  1536, 512, 1536, wcch, wccl);
    conv_split<<<conv_blocks(1536, 512), 256>>>(W_ih, 1600, 1024, 1536, 512, 1536, wcfh, wcfl);
    conv_split<<<conv_blocks(1536, 576), 256>>>(Wg, 576, 0, 1536, 576, 1536, wgh, wgl);
    conv_split<<<conv_blocks(1024, 576), 256>>>(X, 576, 0, 960, 576, 1024, xh, xl);
    conv_split<<<conv_blocks(32000, 512), 256>>>(W_pr, 512, 0, 32000, 512, 32000, wph, wpl);

    // ---- precompute GEMMs (HMMA) ----
    mma_gemm<<<dim3(13, 4),  256, GSMEM>>>(cmh, cml, cwmh, cwml, 512, cb_m, kc, 1600, 512, 0);
    mma_gemm<<<dim3(13, 4),  256, GSMEM>>>(fmh, fml, fwmh, fwml, 512, fb_m, kf, 1600, 512, 0);
    mma_gemm<<<dim3(13, 12), 256, GSMEM>>>(cmh, cml, wcch, wccl, 512, nullptr, Pc, 1600, GDIM, 0);
    mma_gemm<<<dim3(13, 12), 256, GSMEM>>>(fmh, fml, wcfh, wcfl, 512, nullptr, Pf, 1600, GDIM, 0);
    mma_gemm<<<dim3(8, 12),  256, GSMEM>>>(xh, xl, wgh, wgl, 576, b_ih, gipre, 960, GDIM, 0);

    // ---- sequential decode (30 steps x 3 launches) ----
    for (int t = 0; t < T_STEPS; t++) {
        step_qgh2<<<160, 256, QGH_SMEM>>>(cW_h, cb_h, fW_h, fb_h, W_hh, b_hh);
        step_score2<<<64, 256>>>(cW_o, cb_o, fW_o, fb_o, c_mask, f_mask);
        step_gate2<<<dim3(4, BATCH), 256>>>(t);
    }

    // ---- deferred vocabulary projection (HMMA) ----
    conv_split<<<conv_blocks(1024, 512), 256>>>(reluh, 512, 0, 960, 512, 1024, rhh, rhl);
    mma_gemm<<<dim3(8, 250), 256, GSMEM>>>(rhh, rhl, wph, wpl, 512, b_pr, out, 960, VOCAB, 1);
}